// round 2
// baseline (speedup 1.0000x reference)
#include <cuda_runtime.h>
#include <cuda_bf16.h>
#include <cstdint>

// ============================================================================
// TernaryLinear: out[8192,4096] = x[8192,4096] @ W[4096,4096]^T + bias
//
// Base-PTX path (harness compiles compute_103 PTX: no tcgen05 allowed).
// x -> per-row scale s, int8 hi/lo split: x ~= s*(256*h + l)  (15.9-bit quant)
// W ternary -> exact int8.
// out = s_row * (256*(H@W^T) + (L@W^T)) + bias, int32 accum via mma.sync s8.
// ============================================================================

#define M_DIM 8192
#define N_DIM 4096
#define K_DIM 4096
#define BM 128
#define BN 128
#define BK 128                    // int8 elems per K tile (128 bytes/row)
#define NKT (K_DIM / BK)          // 32
#define NSTAGE 4
#define STAGE_BYTES (3 * BM * BK) // A_hi + A_lo + B = 48 KB
#define SMEM_TOTAL (NSTAGE * STAGE_BYTES)

// Static device scratch (sanctioned workaround for no-alloc rule)
__device__ __align__(128) int8_t g_xh8[(size_t)M_DIM * K_DIM];
__device__ __align__(128) int8_t g_xl8[(size_t)M_DIM * K_DIM];
__device__ __align__(128) int8_t g_w8 [(size_t)N_DIM * K_DIM];
__device__ __align__(128) float  g_scale[M_DIM];

// ---------------------------------------------------------------------------
// PTX helpers
// ---------------------------------------------------------------------------
__device__ __forceinline__ uint32_t smem_u32(const void* p) {
    uint32_t a;
    asm("{ .reg .u64 t; cvta.to.shared.u64 t, %1; cvt.u32.u64 %0, t; }"
        : "=r"(a) : "l"(p));
    return a;
}

#define CP16(dst, src) \
    asm volatile("cp.async.cg.shared.global [%0], [%1], 16;" \
                 :: "r"((uint32_t)(dst)), "l"(src) : "memory")

#define CP_COMMIT() asm volatile("cp.async.commit_group;" ::: "memory")
#define CP_WAIT2()  asm volatile("cp.async.wait_group 2;" ::: "memory")

#define LDSM4(r0, r1, r2, r3, addr) \
    asm volatile("ldmatrix.sync.aligned.m8n8.x4.shared.b16 {%0,%1,%2,%3}, [%4];" \
                 : "=r"(r0), "=r"(r1), "=r"(r2), "=r"(r3) : "r"(addr))

__device__ __forceinline__ void mma_s8(int c[4], const uint32_t a[4],
                                       uint32_t b0, uint32_t b1) {
    asm volatile(
        "mma.sync.aligned.m16n8k32.row.col.s32.s8.s8.s32 "
        "{%0,%1,%2,%3}, {%4,%5,%6,%7}, {%8,%9}, {%0,%1,%2,%3};"
        : "+r"(c[0]), "+r"(c[1]), "+r"(c[2]), "+r"(c[3])
        : "r"(a[0]), "r"(a[1]), "r"(a[2]), "r"(a[3]), "r"(b0), "r"(b1));
}

// ---------------------------------------------------------------------------
// Pre-pass 1: per-row quantize x into int8 hi/lo + row scale
// One block (256 thr) per row; row data lives in registers (16 floats/thread)
// ---------------------------------------------------------------------------
__global__ void __launch_bounds__(256) quant_x_kernel(const float* __restrict__ x) {
    const int row = blockIdx.x;
    const int t = threadIdx.x;
    const float4* xr = reinterpret_cast<const float4*>(x + (size_t)row * K_DIM);

    float4 v[4];
    float amax = 0.f;
#pragma unroll
    for (int p = 0; p < 4; ++p) {
        v[p] = xr[p * 256 + t];
        amax = fmaxf(amax, fmaxf(fmaxf(fabsf(v[p].x), fabsf(v[p].y)),
                                 fmaxf(fabsf(v[p].z), fabsf(v[p].w))));
    }
#pragma unroll
    for (int o = 16; o; o >>= 1)
        amax = fmaxf(amax, __shfl_xor_sync(0xFFFFFFFFu, amax, o));

    __shared__ float smax[8];
    if ((t & 31) == 0) smax[t >> 5] = amax;
    __syncthreads();
    float bmax = fmaxf(fmaxf(fmaxf(smax[0], smax[1]), fmaxf(smax[2], smax[3])),
                       fmaxf(fmaxf(smax[4], smax[5]), fmaxf(smax[6], smax[7])));

    const float inv = (bmax > 0.f) ? (32639.f / bmax) : 0.f;
    if (t == 0) g_scale[row] = (bmax > 0.f) ? (bmax / 32639.f) : 0.f;

    char4* hp = reinterpret_cast<char4*>(g_xh8 + (size_t)row * K_DIM);
    char4* lp = reinterpret_cast<char4*>(g_xl8 + (size_t)row * K_DIM);
#pragma unroll
    for (int p = 0; p < 4; ++p) {
        int q0 = __float2int_rn(v[p].x * inv);
        int q1 = __float2int_rn(v[p].y * inv);
        int q2 = __float2int_rn(v[p].z * inv);
        int q3 = __float2int_rn(v[p].w * inv);
        int h0 = (q0 + 128) >> 8, h1 = (q1 + 128) >> 8;
        int h2 = (q2 + 128) >> 8, h3 = (q3 + 128) >> 8;
        char4 hc = make_char4((char)h0, (char)h1, (char)h2, (char)h3);
        char4 lc = make_char4((char)(q0 - (h0 << 8)), (char)(q1 - (h1 << 8)),
                              (char)(q2 - (h2 << 8)), (char)(q3 - (h3 << 8)));
        hp[p * 256 + t] = hc;
        lp[p * 256 + t] = lc;
    }
}

// ---------------------------------------------------------------------------
// Pre-pass 2: W float{-1,0,1} -> int8 (exact)
// ---------------------------------------------------------------------------
__global__ void __launch_bounds__(256) quant_w_kernel(const float* __restrict__ w) {
    size_t i = (size_t)blockIdx.x * 256 + threadIdx.x;   // float4 index
    float4 v = reinterpret_cast<const float4*>(w)[i];
    char4 c = make_char4((char)__float2int_rn(v.x), (char)__float2int_rn(v.y),
                         (char)__float2int_rn(v.z), (char)__float2int_rn(v.w));
    reinterpret_cast<char4*>(g_w8)[i] = c;
}

// ---------------------------------------------------------------------------
// Main int8 GEMM: CTA 128x128, BK=128, 4-stage cp.async, mma.sync m16n8k32.s8
// 512 threads = 16 warps in 4x4 grid; warp tile 32x32, two passes (hi/lo).
// SMEM stage layout: [A_hi 16K][A_lo 16K][B 16K], rows 128B, SW128 swizzle.
// ---------------------------------------------------------------------------
__global__ void __launch_bounds__(512, 1)
gemm_s8_kernel(const float* __restrict__ bias, float* __restrict__ out) {
    extern __shared__ char smem[];
    const uint32_t sb = smem_u32(smem);
    const int tid = threadIdx.x;
    const int lane = tid & 31;
    const int wid = tid >> 5;
    const int wm = wid >> 2;           // 0..3 (m)
    const int wn = wid & 3;            // 0..3 (n)
    const int m0 = blockIdx.y * BM;
    const int n0 = blockIdx.x * BN;

    // --- cp.async thread mapping: thread t -> row t/4, chunks (t%4)*2, +1 ---
    const int pr = tid >> 2;           // 0..127
    const int pc = (tid & 3) * 2;
    const int8_t* gH = g_xh8 + (size_t)(m0 + pr) * K_DIM;
    const int8_t* gL = g_xl8 + (size_t)(m0 + pr) * K_DIM;
    const int8_t* gW = g_w8  + (size_t)(n0 + pr) * K_DIM;
    const uint32_t prBase = (uint32_t)pr * BK;
    const uint32_t sw0 = prBase + (uint32_t)(((pc + 0) ^ (pr & 7)) << 4);
    const uint32_t sw1 = prBase + (uint32_t)(((pc + 1) ^ (pr & 7)) << 4);

#define PREFETCH(it, stage) do {                                              \
    const int _k0 = (it) * BK;                                                \
    const uint32_t _s = sb + (uint32_t)(stage) * STAGE_BYTES;                 \
    CP16(_s + sw0,         gH + _k0 + (pc + 0) * 16);                         \
    CP16(_s + sw1,         gH + _k0 + (pc + 1) * 16);                         \
    CP16(_s + 16384 + sw0, gL + _k0 + (pc + 0) * 16);                         \
    CP16(_s + 16384 + sw1, gL + _k0 + (pc + 1) * 16);                         \
    CP16(_s + 32768 + sw0, gW + _k0 + (pc + 0) * 16);                         \
    CP16(_s + 32768 + sw1, gW + _k0 + (pc + 1) * 16);                         \
} while (0)

    // --- ldmatrix lane addressing (offsets within a stage) ---
    // A: matrices g0..g3 = [r0-7,k0-15],[r8-15,k0-15],[r0-7,k16-31],[r8-15,k16-31]
    const int ag = lane >> 3;                       // 0..3
    const int aRow0 = wm * 32 + ((ag & 1) << 3) + (lane & 7);   // mt=0 row
    const int agc = ag >> 1;                        // chunk half (0/1)
    // B: x4 over n-rows 0..31 at one 16B k-chunk
    const int bRow = wn * 32 + lane;
    const uint32_t bRowOff = 32768u + (uint32_t)bRow * BK;
    const int bRowSw = bRow & 7;

    int accH[2][4][4], accL[2][4][4];
#pragma unroll
    for (int mt = 0; mt < 2; ++mt)
#pragma unroll
        for (int nt = 0; nt < 4; ++nt)
#pragma unroll
            for (int i = 0; i < 4; ++i) { accH[mt][nt][i] = 0; accL[mt][nt][i] = 0; }

    // --- prologue: fill 3 stages ---
    PREFETCH(0, 0); CP_COMMIT();
    PREFETCH(1, 1); CP_COMMIT();
    PREFETCH(2, 2); CP_COMMIT();

    for (int it = 0; it < NKT; ++it) {
        CP_WAIT2();
        __syncthreads();
        if (it + 3 < NKT) { PREFETCH(it + 3, (it + 3) & 3); }
        CP_COMMIT();

        const uint32_t S = sb + (uint32_t)(it & 3) * STAGE_BYTES;
#pragma unroll
        for (int ks = 0; ks < 4; ++ks) {
            // B fragments: b0 (chunk 2ks), b1 (chunk 2ks+1) for 4 n-tiles
            uint32_t b0[4], b1[4];
            {
                uint32_t a0 = S + bRowOff + (uint32_t)(((ks * 2)     ^ bRowSw) << 4);
                uint32_t a1 = S + bRowOff + (uint32_t)(((ks * 2 + 1) ^ bRowSw) << 4);
                LDSM4(b0[0], b0[1], b0[2], b0[3], a0);
                LDSM4(b1[0], b1[1], b1[2], b1[3], a1);
            }
            uint32_t ah[2][4], al[2][4];
#pragma unroll
            for (int mt = 0; mt < 2; ++mt) {
                const int rA = aRow0 + mt * 16;
                const int cA = ks * 2 + agc;
                const uint32_t off = (uint32_t)rA * BK +
                                     (uint32_t)((cA ^ (rA & 7)) << 4);
                LDSM4(ah[mt][0], ah[mt][1], ah[mt][2], ah[mt][3], S + off);
                LDSM4(al[mt][0], al[mt][1], al[mt][2], al[mt][3], S + 16384u + off);
            }
#pragma unroll
            for (int mt = 0; mt < 2; ++mt)
#pragma unroll
                for (int nt = 0; nt < 4; ++nt) {
                    mma_s8(accH[mt][nt], ah[mt], b0[nt], b1[nt]);
                    mma_s8(accL[mt][nt], al[mt], b0[nt], b1[nt]);
                }
        }
    }

    // --- epilogue: combine hi/lo, scale, bias, store fp32 ---
#pragma unroll
    for (int mt = 0; mt < 2; ++mt) {
        const int r0 = m0 + wm * 32 + mt * 16 + (lane >> 2);
        const float s0 = g_scale[r0];
        const float s1 = g_scale[r0 + 8];
#pragma unroll
        for (int nt = 0; nt < 4; ++nt) {
            const int col = n0 + wn * 32 + nt * 8 + 2 * (lane & 3);
            const float bv0 = __ldg(bias + col);
            const float bv1 = __ldg(bias + col + 1);
            const int* h = accH[mt][nt];
            const int* l = accL[mt][nt];
            float2 o0, o1;
            o0.x = s0 * (float)(256 * h[0] + l[0]) + bv0;
            o0.y = s0 * (float)(256 * h[1] + l[1]) + bv1;
            o1.x = s1 * (float)(256 * h[2] + l[2]) + bv0;
            o1.y = s1 * (float)(256 * h[3] + l[3]) + bv1;
            *reinterpret_cast<float2*>(out + (size_t)r0 * N_DIM + col) = o0;
            *reinterpret_cast<float2*>(out + (size_t)(r0 + 8) * N_DIM + col) = o1;
        }
    }
#undef PREFETCH
}

// ---------------------------------------------------------------------------
// Launch
// ---------------------------------------------------------------------------
extern "C" void kernel_launch(void* const* d_in, const int* in_sizes, int n_in,
                              void* d_out, int out_size) {
    const float* x    = (const float*)d_in[0];
    const float* w    = (const float*)d_in[1];
    const float* bias = (const float*)d_in[2];
    float* out = (float*)d_out;

    quant_x_kernel<<<M_DIM, 256>>>(x);                       // 8192 blocks
    quant_w_kernel<<<(N_DIM * K_DIM / 4) / 256, 256>>>(w);   // 16384 blocks

    cudaFuncSetAttribute(gemm_s8_kernel,
                         cudaFuncAttributeMaxDynamicSharedMemorySize, SMEM_TOTAL);
    dim3 grid(N_DIM / BN, M_DIM / BM);   // (32, 64): n fastest -> W L2-resident
    gemm_s8_kernel<<<grid, 512, SMEM_TOTAL>>>(bias, out);
}